// round 15
// baseline (speedup 1.0000x reference)
#include <cuda_runtime.h>
#include <cuda_fp16.h>
#include <cstdint>

#define NROWS 16384
#define INDIM 768
#define DD    128
#define NITEMS2 (128 * 256)   // 128 q-tiles x 256 k-chunks (64 cols each)

// ---------------- device scratch (no allocs allowed) ----------------
__device__ float g_wvfc[DD];
__device__ float g_bu_p;
__device__ float g_bu;
__device__ float g_wu[INDIM];
__device__ float g_bqk[256];
__device__ float g_u[NROWS];   // stores 0.5*u (sig*u = uh*tanh(0.5s) + uh)
__device__ __align__(16) __half g_xhi[NROWS * INDIM];
__device__ __align__(16) __half g_wTh[256 * INDIM];
__device__ __align__(16) __half g_qf[NROWS * DD];   // stores 0.5*q
__device__ __align__(16) __half g_kf[NROWS * DD];

// ---------------- PTX helpers (base ISA only) -------------------------
__device__ __forceinline__ uint32_t smem_u32(const void* p) {
    uint32_t a;
    asm("{ .reg .u64 t; cvta.to.shared.u64 t, %1; cvt.u32.u64 %0, t; }" : "=r"(a) : "l"(p));
    return a;
}
#define CP_ASYNC16(dst, src) asm volatile("cp.async.cg.shared.global [%0], [%1], 16;" :: "r"(dst), "l"(src) : "memory")
#define CP_COMMIT()          asm volatile("cp.async.commit_group;" ::: "memory")
#define CP_WAIT(n)           asm volatile("cp.async.wait_group %0;" :: "n"(n) : "memory")
#define BAR_G(id)            asm volatile("bar.sync %0, %1;" :: "r"(id), "r"(128) : "memory")

__device__ __forceinline__ void ldsm4(uint32_t* r, uint32_t addr) {
    asm volatile("ldmatrix.sync.aligned.m8n8.x4.shared.b16 {%0,%1,%2,%3}, [%4];"
                 : "=r"(r[0]), "=r"(r[1]), "=r"(r[2]), "=r"(r[3]) : "r"(addr));
}
__device__ __forceinline__ void mma_f16(float* c, const uint32_t* a, const uint32_t* b) {
    asm volatile("mma.sync.aligned.m16n8k16.row.col.f32.f16.f16.f32 "
                 "{%0,%1,%2,%3}, {%4,%5,%6,%7}, {%8,%9}, {%0,%1,%2,%3};"
                 : "+f"(c[0]), "+f"(c[1]), "+f"(c[2]), "+f"(c[3])
                 : "r"(a[0]), "r"(a[1]), "r"(a[2]), "r"(a[3]), "r"(b[0]), "r"(b[1]));
}
__device__ __forceinline__ float tanh_ap(float x) {
    float r;
    asm("tanh.approx.f32 %0, %1;" : "=f"(r) : "f"(x));
    return r;
}

// ---------------- P1/P2: tiny weight precompute -----------------------
__global__ void k_p1(const float* __restrict__ W_qkv, const float* __restrict__ W_fc,
                     const float* __restrict__ b_qkv) {
    int d = threadIdx.x;
    float acc = 0.f;
    for (int e = 0; e < DD; e++) acc += W_qkv[d * 3 * DD + 2 * DD + e] * W_fc[e];
    g_wvfc[d] = acc;
    if (d == 0) {
        float b = 0.f;
        for (int e = 0; e < DD; e++) b += b_qkv[2 * DD + e] * W_fc[e];
        g_bu_p = b;
    }
}
__global__ void k_p2(const float* __restrict__ W_token, const float* __restrict__ W_qkv) {
    __shared__ float wt[DD];
    int t = blockIdx.x, n = threadIdx.x;
    if (n < DD) wt[n] = W_token[t * DD + n];
    __syncthreads();
    float acc = 0.f;
    for (int d = 0; d < DD; d++) acc += wt[d] * W_qkv[d * 3 * DD + n];
    g_wTh[n * INDIM + t] = __float2half_rn(acc);
    if (n == 0) {
        float a = 0.f;
        for (int d = 0; d < DD; d++) a += wt[d] * g_wvfc[d];
        g_wu[t] = a;
    }
}
__global__ void k_p3z(const float* __restrict__ b_token, const float* __restrict__ W_qkv,
                      const float* __restrict__ b_qkv, const float* __restrict__ b_fc,
                      float* __restrict__ out) {
    int n = threadIdx.x;
    if (blockIdx.x == 0) {
        float acc = 0.f;
        for (int d = 0; d < DD; d++) acc += b_token[d] * W_qkv[d * 3 * DD + n];
        g_bqk[n] = acc + b_qkv[n];
        if (n == 0) {
            float a = 0.f;
            for (int d = 0; d < DD; d++) a += b_token[d] * g_wvfc[d];
            g_bu = a + g_bu_p;
        }
    }
    out[blockIdx.x * 256 + n] = b_fc[0];
}

// ---------------- x -> fp16 split + u matvec (one warp per row) --------
__global__ __launch_bounds__(256) void k_xu(const float* __restrict__ x) {
    int row = blockIdx.x * 8 + (threadIdx.x >> 5);
    int lane = threadIdx.x & 31;
    const float* xr = x + (long)row * INDIM;
    __half* xh = g_xhi + (long)row * INDIM;
    float acc = 0.f;
#pragma unroll
    for (int i = 0; i < 6; i++) {
        int c = i * 128 + lane * 4;
        float4 v = *(const float4*)(xr + c);
        float4 wv = *(const float4*)(g_wu + c);
        acc += v.x * wv.x + v.y * wv.y + v.z * wv.z + v.w * wv.w;
        *(__half2*)(xh + c) = __floats2half2_rn(v.x, v.y);
        *(__half2*)(xh + c + 2) = __floats2half2_rn(v.z, v.w);
    }
#pragma unroll
    for (int off = 16; off; off >>= 1) acc += __shfl_xor_sync(0xFFFFFFFFu, acc, off);
    if (lane == 0) g_u[row] = 0.5f * (acc + g_bu);
}

// ---------------- projection GEMM (HMMA fp16, 1 pass per half) ---------
#define PJ_STG  32768
#define PJ_SMEM (2 * PJ_STG)
__global__ __launch_bounds__(256, 1) void k_projh() {
    extern __shared__ char smem[];
    uint32_t sb = smem_u32(smem);
    int tid = threadIdx.x, lane = tid & 31, w = tid >> 5;
    int row0 = blockIdx.x * 128;
    int half = blockIdx.y;
    const __half* wh = g_wTh + (long)half * 128 * INDIM;

#define PJ_LOAD(buf, kc)                                                          \
    do {                                                                          \
        uint32_t base_ = sb + (buf) * PJ_STG;                                     \
        _Pragma("unroll")                                                         \
        for (int t_ = 0; t_ < 4; t_++) {                                          \
            int idx_ = t_ * 256 + tid;                                            \
            int r_ = idx_ >> 3, cu_ = idx_ & 7;                                   \
            uint32_t off_ = (uint32_t)r_ * 128u + (uint32_t)((cu_ ^ (r_ & 7)) << 4); \
            CP_ASYNC16(base_ + off_,         g_xhi + (long)(row0 + r_) * INDIM + (kc) + cu_ * 8); \
            CP_ASYNC16(base_ + 16384 + off_, wh + (long)r_ * INDIM + (kc) + cu_ * 8); \
        }                                                                         \
        CP_COMMIT();                                                              \
    } while (0)

    PJ_LOAD(0, 0);

    float acc[16][4];
#pragma unroll
    for (int nb = 0; nb < 16; nb++) {
        acc[nb][0] = 0.f; acc[nb][1] = 0.f; acc[nb][2] = 0.f; acc[nb][3] = 0.f;
    }

    int rA = 16 * w + (lane & 15);
    int cuA = lane >> 4;
    uint32_t rbA = (uint32_t)rA * 128u;
    int xA = rA & 7;
    int rB = (lane & 7) + ((lane & 16) >> 1);
    int cB = (lane >> 3) & 1;
    uint32_t uB = (uint32_t)rB * 128u;
    int xB = rB & 7;

    for (int s = 0; s < 12; s++) {
        if (s + 1 < 12) {
            PJ_LOAD((s + 1) & 1, (s + 1) * 64);
            CP_WAIT(1);
        } else {
            CP_WAIT(0);
        }
        __syncthreads();
        uint32_t base = sb + (s & 1) * PJ_STG;
#pragma unroll
        for (int kk = 0; kk < 4; kk++) {
            uint32_t Ah[4];
            uint32_t aoff = rbA + (uint32_t)(((kk * 2 + cuA) ^ xA) << 4);
            ldsm4(Ah, base + aoff);
            uint32_t coff = (uint32_t)(((kk * 2 + cB) ^ xB) << 4);
            uint32_t bh[8][4];
#pragma unroll
            for (int p = 0; p < 8; p++) ldsm4(bh[p], base + 16384 + p * 2048 + uB + coff);
#pragma unroll
            for (int p = 0; p < 8; p++) {
                mma_f16(acc[2 * p], Ah, &bh[p][0]);
                mma_f16(acc[2 * p + 1], Ah, &bh[p][2]);
            }
        }
        __syncthreads();
    }

    __half* dst = half ? g_kf : g_qf;
    float scale = half ? 1.0f : 0.5f;
    int r0 = row0 + 16 * w + (lane >> 2);
#pragma unroll
    for (int nb = 0; nb < 16; nb++) {
        int c = nb * 8 + (lane & 3) * 2;
        float b0 = g_bqk[half * 128 + c];
        float b1 = g_bqk[half * 128 + c + 1];
        *(__half2*)(dst + (long)r0 * DD + c) =
            __floats2half2_rn(scale * (acc[nb][0] + b0), scale * (acc[nb][1] + b1));
        *(__half2*)(dst + (long)(r0 + 8) * DD + c) =
            __floats2half2_rn(scale * (acc[nb][2] + b0), scale * (acc[nb][3] + b1));
    }
}

// ---------------- attention: two anti-phase warp-groups ---------------
// Item = 128 q-rows x 64 k-cols (16KB K chunk). Group A (warps 0-3) does
// MMA;EPI per item; group B (warps 4-7) does EPI(prev);MMA — so on each
// SMSP one warp feeds the tensor pipe while the other issues MUFU tanh.
// Per-group K double buffer (2x16KB), u triple buffer (3x256B).
#define SO_US  65536
#define AT_SMEM (65536 + 2048)

__global__ __launch_bounds__(256, 1) void k_attn(float* __restrict__ out) {
    extern __shared__ char smem[];
    uint32_t sb = smem_u32(smem);
    int tid = threadIdx.x, lane = tid & 31, w = tid >> 5;
    int g = w >> 2;        // warp-group 0/1
    int mg = w & 3;        // warp-in-group (SMSP index)
    int tg = tid & 127;    // thread-in-group
    const int late = g;    // group B runs epilogue one item behind

    int startc = (int)((long)blockIdx.x * NITEMS2 / gridDim.x);
    int endc = (int)((long)(blockIdx.x + 1) * NITEMS2 / gridDim.x);
    int L = endc - startc;
    int cnt = (L - g + 1) >> 1;   // items for this group: startc+g, +2, ...

    uint32_t kgb = sb + g * 32768;            // this group's K buffers
    char* usp = smem + SO_US + g * 768;       // this group's u slots

    int rB = (lane & 7) + ((lane & 16) >> 1);
    int cB = (lane >> 3) & 1;
    uint32_t uB = (uint32_t)rB * 256u;
    int xB = rB & 7;
    const int cl = (lane & 3) * 2;

    uint32_t Ah[2][8][4];
    float acc[2][8][4];
    float o00 = 0.f, o01 = 0.f, o10 = 0.f, o11 = 0.f;
    int oit = -1, qit = -1;

#define PREFETCH_G(IDX, BUF, USLOT)                                             \
    do {                                                                        \
        int jn_ = (IDX) & 255;                                                  \
        const __half* sh_ = g_kf + (long)jn_ * 64 * DD;                         \
        uint32_t kb_ = kgb + (BUF) * 16384;                                     \
        _Pragma("unroll")                                                       \
        for (int t_ = 0; t_ < 8; t_++) {                                        \
            int iu_ = t_ * 128 + tg;                                            \
            int r_ = iu_ >> 4, cu_ = iu_ & 15;                                  \
            uint32_t off_ = (uint32_t)r_ * 256u + (uint32_t)((cu_ ^ (r_ & 7)) << 4); \
            CP_ASYNC16(kb_ + off_, sh_ + (long)r_ * DD + cu_ * 8);              \
        }                                                                       \
        if (tg < 16) CP_ASYNC16(smem_u32(usp) + (USLOT) * 256 + tg * 16,        \
                                g_u + jn_ * 64 + tg * 4);                       \
        CP_COMMIT();                                                            \
    } while (0)

#define FLUSH()                                                                 \
    do {                                                                        \
        _Pragma("unroll")                                                       \
        for (int s_ = 1; s_ <= 2; s_ <<= 1) {                                   \
            o00 += __shfl_xor_sync(0xFFFFFFFFu, o00, s_);                       \
            o01 += __shfl_xor_sync(0xFFFFFFFFu, o01, s_);                       \
            o10 += __shfl_xor_sync(0xFFFFFFFFu, o10, s_);                       \
            o11 += __shfl_xor_sync(0xFFFFFFFFu, o11, s_);                       \
        }                                                                       \
        if ((lane & 3) == 0) {                                                  \
            int r_ = oit * 128 + mg * 32 + (lane >> 2);                         \
            atomicAdd(out + r_, o00);                                           \
            atomicAdd(out + r_ + 8, o01);                                       \
            atomicAdd(out + r_ + 16, o10);                                      \
            atomicAdd(out + r_ + 24, o11);                                      \
        }                                                                       \
    } while (0)

#define MMA_G(IDX, B)                                                           \
    do {                                                                        \
        int nit_ = (IDX) >> 8;                                                  \
        if (nit_ != qit) {                                                      \
            qit = nit_;                                                         \
            _Pragma("unroll")                                                   \
            for (int mf = 0; mf < 2; mf++) {                                    \
                const __half* qb_ =                                             \
                    g_qf + ((long)qit * 128 + mg * 32 + mf * 16 + (lane >> 2)) * DD + cl; \
                _Pragma("unroll")                                               \
                for (int kk = 0; kk < 8; kk++) {                                \
                    Ah[mf][kk][0] = *(const uint32_t*)(qb_ + kk * 16);          \
                    Ah[mf][kk][1] = *(const uint32_t*)(qb_ + 8 * DD + kk * 16); \
                    Ah[mf][kk][2] = *(const uint32_t*)(qb_ + kk * 16 + 8);      \
                    Ah[mf][kk][3] = *(const uint32_t*)(qb_ + 8 * DD + kk * 16 + 8); \
                }                                                               \
            }                                                                   \
        }                                                                       \
        _Pragma("unroll")                                                       \
        for (int mf = 0; mf < 2; mf++)                                          \
            _Pragma("unroll")                                                   \
            for (int nb = 0; nb < 8; nb++) {                                    \
                acc[mf][nb][0] = 0.f; acc[mf][nb][1] = 0.f;                     \
                acc[mf][nb][2] = 0.f; acc[mf][nb][3] = 0.f;                     \
            }                                                                   \
        uint32_t kb_ = kgb + (B) * 16384;                                       \
        _Pragma("unroll")                                                       \
        for (int kk = 0; kk < 8; kk++) {                                        \
            uint32_t coff_ = (uint32_t)(((kk * 2 + cB) ^ xB) << 4);             \
            uint32_t bh_[4][4];                                                 \
            _Pragma("unroll")                                                   \
            for (int p = 0; p < 4; p++) ldsm4(bh_[p], kb_ + p * 4096 + uB + coff_); \
            _Pragma("unroll")                                                   \
            for (int p = 0; p < 4; p++) {                                       \
                mma_f16(acc[0][2 * p], Ah[0][kk], &bh_[p][0]);                  \
                mma_f16(acc[0][2 * p + 1], Ah[0][kk], &bh_[p][2]);              \
                mma_f16(acc[1][2 * p], Ah[1][kk], &bh_[p][0]);                  \
                mma_f16(acc[1][2 * p + 1], Ah[1][kk], &bh_[p][2]);              \
            }                                                                   \
        }                                                                       \
    } while (0)

#define EPI_G(USLOT, EIDX)                                                      \
    do {                                                                        \
        int eit_ = (EIDX) >> 8;                                                 \
        if (eit_ != oit) {                                                      \
            if (oit >= 0) FLUSH();                                              \
            oit = eit_;                                                         \
            o00 = 0.f; o01 = 0.f; o10 = 0.f; o11 = 0.f;                         \
        }                                                                       \
        const float* Us_ = (const float*)(usp + (USLOT) * 256);                 \
        float ts_ = 0.f;                                                        \
        _Pragma("unroll")                                                       \
        for (int nb = 0; nb < 8; nb++) {                                        \
            float2 u2_ = *(const float2*)(Us_ + nb * 8 + cl);                   \
            ts_ += u2_.x + u2_.y;                                               \
            float t0_ = tanh_ap(acc[0][nb][0]);                                 \
            float t1_ = tanh_ap(acc[0][nb][1]);                                 \
            float t2_ = tanh_ap(acc[0][nb][2]);                                 \
            float t3_ = tanh_ap(acc[0][nb][3]);                                 \
            o00 = fmaf(t0_, u2_.x, o00); o00 = fmaf(t1_, u2_.y, o00);           \
            o01 = fmaf(t2_, u2_.x, o01); o01 = fmaf(t3_, u2_.y, o01);           \
            t0_ = tanh_ap(acc[1][nb][0]);                                       \
            t1_ = tanh_ap(acc[1][nb][1]);                                       \
            t2_ = tanh_ap(acc[1][nb][2]);                                       \
            t3_ = tanh_ap(acc[1][nb][3]);                                       \
            o10 = fmaf(t0_, u2_.x, o10); o10 = fmaf(t1_, u2_.y, o10);           \
            o11 = fmaf(t2_, u2_.x, o11); o11 = fmaf(t3_, u2_.y, o11);           \
        }                                                                       \
        o00 += ts_; o01 += ts_; o10 += ts_; o11 += ts_;                         \
    } while (0)

    if (cnt > 0) PREFETCH_G(startc + g, 0, 0);

    for (int n = 0; n < cnt; n++) {
        int idx = startc + g + 2 * n;
        int b = n & 1;
        BAR_G(1 + g);   // all group warps done reading buf b^1 (item n-1)
        if (n + 1 < cnt) {
            PREFETCH_G(idx + 2, b ^ 1, (n + 1) % 3);
            CP_WAIT(1);
        } else {
            CP_WAIT(0);
        }
        BAR_G(1 + g);   // buf b (item n) resident
        if (late && n > 0) EPI_G((n - 1) % 3, idx - 2);
        MMA_G(idx, b);
        if (!late) EPI_G(n % 3, idx);
    }
    if (late && cnt > 0) EPI_G((cnt - 1) % 3, startc + g + 2 * (cnt - 1));
    if (oit >= 0) FLUSH();
}

// ---------------- launch ----------------------------------------------
extern "C" void kernel_launch(void* const* d_in, const int* in_sizes, int n_in,
                              void* d_out, int out_size) {
    const float* x       = (const float*)d_in[0];
    const float* W_token = (const float*)d_in[2];
    const float* b_token = (const float*)d_in[3];
    const float* W_qkv   = (const float*)d_in[4];
    const float* b_qkv   = (const float*)d_in[5];
    const float* W_fc    = (const float*)d_in[6];
    const float* b_fc    = (const float*)d_in[7];
    float* out = (float*)d_out;

    int nsm = 148;
    cudaDeviceGetAttribute(&nsm, cudaDevAttrMultiProcessorCount, 0);

    cudaFuncSetAttribute(k_attn, cudaFuncAttributeMaxDynamicSharedMemorySize, AT_SMEM);
    cudaFuncSetAttribute(k_projh, cudaFuncAttributeMaxDynamicSharedMemorySize, PJ_SMEM);

    k_p1<<<1, 128>>>(W_qkv, W_fc, b_qkv);
    k_p2<<<768, 256>>>(W_token, W_qkv);
    k_p3z<<<NROWS / 256, 256>>>(b_token, W_qkv, b_qkv, b_fc, out);
    k_xu<<<NROWS / 8, 256>>>(x);
    k_projh<<<dim3(128, 2), 256, PJ_SMEM>>>();
    k_attn<<<nsm, 256, AT_SMEM>>>(out);
}

// round 16
// speedup vs baseline: 1.0917x; 1.0917x over previous
#include <cuda_runtime.h>
#include <cuda_fp16.h>
#include <cstdint>

#define NROWS 16384
#define INDIM 768
#define DD    128
#define BN    128
#define NJT   (NROWS / BN)
#define NITEMS (128 * NJT)

// ---------------- device scratch (no allocs allowed) ----------------
__device__ float g_wu[INDIM];
__device__ float g_bqk[256];
__device__ float g_bu;
__device__ float g_u[NROWS];   // stores 0.5*u (sig*u = uh*tanh(0.5s) + uh)
__device__ __align__(16) __half g_xhi[NROWS * INDIM];
__device__ __align__(16) __half g_wTh[256 * INDIM];
__device__ __align__(16) __half g_qf[NROWS * DD];   // stores 0.5*q
__device__ __align__(16) __half g_kf[NROWS * DD];

// ---------------- PTX helpers (base ISA only) -------------------------
__device__ __forceinline__ uint32_t smem_u32(const void* p) {
    uint32_t a;
    asm("{ .reg .u64 t; cvta.to.shared.u64 t, %1; cvt.u32.u64 %0, t; }" : "=r"(a) : "l"(p));
    return a;
}
#define CP_ASYNC16(dst, src) asm volatile("cp.async.cg.shared.global [%0], [%1], 16;" :: "r"(dst), "l"(src) : "memory")
#define CP_COMMIT()          asm volatile("cp.async.commit_group;" ::: "memory")
#define CP_WAIT(n)           asm volatile("cp.async.wait_group %0;" :: "n"(n) : "memory")

__device__ __forceinline__ void ldsm4(uint32_t* r, uint32_t addr) {
    asm volatile("ldmatrix.sync.aligned.m8n8.x4.shared.b16 {%0,%1,%2,%3}, [%4];"
                 : "=r"(r[0]), "=r"(r[1]), "=r"(r[2]), "=r"(r[3]) : "r"(addr));
}
__device__ __forceinline__ void mma_f16(float* c, const uint32_t* a, const uint32_t* b) {
    asm volatile("mma.sync.aligned.m16n8k16.row.col.f32.f16.f16.f32 "
                 "{%0,%1,%2,%3}, {%4,%5,%6,%7}, {%8,%9}, {%0,%1,%2,%3};"
                 : "+f"(c[0]), "+f"(c[1]), "+f"(c[2]), "+f"(c[3])
                 : "r"(a[0]), "r"(a[1]), "r"(a[2]), "r"(a[3]), "r"(b[0]), "r"(b[1]));
}
__device__ __forceinline__ float tanh_ap(float x) {
    float r;
    asm("tanh.approx.f32 %0, %1;" : "=f"(r) : "f"(x));
    return r;
}

// ---------------- k_pre: all weight precompute in one launch -----------
// Block t (0..767): row t of W_token @ W_qkv[:, :384].
//   n < 256  -> g_wTh[n*768+t] (fused q/k weight, transposed fp16)
//   n >= 256 -> v-column; reduce against W_fc -> g_wu[t]
// Block 768: same with b_token -> g_bqk (+b_qkv) and g_bu.
__global__ __launch_bounds__(384) void k_pre(const float* __restrict__ W_token,
                                             const float* __restrict__ b_token,
                                             const float* __restrict__ W_qkv,
                                             const float* __restrict__ b_qkv,
                                             const float* __restrict__ W_fc) {
    __shared__ float wt[DD];
    __shared__ float vcol[DD];
    int t = blockIdx.x, n = threadIdx.x;
    bool isb = (t == 768);
    if (n < DD) wt[n] = isb ? b_token[n] : W_token[t * DD + n];
    __syncthreads();
    float acc = 0.f;
    for (int d = 0; d < DD; d++) acc += wt[d] * W_qkv[d * 3 * DD + n];
    if (isb) acc += b_qkv[n];
    if (n < 256) {
        if (isb) g_bqk[n] = acc;
        else g_wTh[n * INDIM + t] = __float2half_rn(acc);
    } else {
        vcol[n - 256] = acc;
    }
    __syncthreads();
    if (n < 32) {
        float a = 0.f;
#pragma unroll
        for (int i = 0; i < 4; i++) a += vcol[n + 32 * i] * W_fc[n + 32 * i];
#pragma unroll
        for (int off = 16; off; off >>= 1) a += __shfl_xor_sync(0xFFFFFFFFu, a, off);
        if (n == 0) {
            if (isb) g_bu = a;
            else g_wu[t] = a;
        }
    }
}

// ---------------- x -> fp16 split + u matvec (one warp per row) --------
__global__ __launch_bounds__(256) void k_xu(const float* __restrict__ x) {
    int row = blockIdx.x * 8 + (threadIdx.x >> 5);
    int lane = threadIdx.x & 31;
    const float* xr = x + (long)row * INDIM;
    __half* xh = g_xhi + (long)row * INDIM;
    float acc = 0.f;
#pragma unroll
    for (int i = 0; i < 6; i++) {
        int c = i * 128 + lane * 4;
        float4 v = *(const float4*)(xr + c);
        float4 wv = *(const float4*)(g_wu + c);
        acc += v.x * wv.x + v.y * wv.y + v.z * wv.z + v.w * wv.w;
        *(__half2*)(xh + c) = __floats2half2_rn(v.x, v.y);
        *(__half2*)(xh + c + 2) = __floats2half2_rn(v.z, v.w);
    }
#pragma unroll
    for (int off = 16; off; off >>= 1) acc += __shfl_xor_sync(0xFFFFFFFFu, acc, off);
    if (lane == 0) g_u[row] = 0.5f * (acc + g_bu);
}

// ---------------- projection GEMM (HMMA fp16, 1 pass per half) ---------
// Also initializes out = b_fc (half-0 CTAs) so k_attn can atomicAdd.
#define PJ_STG  32768
#define PJ_SMEM (2 * PJ_STG)
__global__ __launch_bounds__(256, 1) void k_projh(const float* __restrict__ b_fc,
                                                  float* __restrict__ out) {
    extern __shared__ char smem[];
    uint32_t sb = smem_u32(smem);
    int tid = threadIdx.x, lane = tid & 31, w = tid >> 5;
    int row0 = blockIdx.x * 128;
    int half = blockIdx.y;
    const __half* wh = g_wTh + (long)half * 128 * INDIM;

    if (half == 0 && tid < 128) out[row0 + tid] = b_fc[0];

#define PJ_LOAD(buf, kc)                                                          \
    do {                                                                          \
        uint32_t base_ = sb + (buf) * PJ_STG;                                     \
        _Pragma("unroll")                                                         \
        for (int t_ = 0; t_ < 4; t_++) {                                          \
            int idx_ = t_ * 256 + tid;                                            \
            int r_ = idx_ >> 3, cu_ = idx_ & 7;                                   \
            uint32_t off_ = (uint32_t)r_ * 128u + (uint32_t)((cu_ ^ (r_ & 7)) << 4); \
            CP_ASYNC16(base_ + off_,         g_xhi + (long)(row0 + r_) * INDIM + (kc) + cu_ * 8); \
            CP_ASYNC16(base_ + 16384 + off_, wh + (long)r_ * INDIM + (kc) + cu_ * 8); \
        }                                                                         \
        CP_COMMIT();                                                              \
    } while (0)

    PJ_LOAD(0, 0);

    float acc[16][4];
#pragma unroll
    for (int nb = 0; nb < 16; nb++) {
        acc[nb][0] = 0.f; acc[nb][1] = 0.f; acc[nb][2] = 0.f; acc[nb][3] = 0.f;
    }

    int rA = 16 * w + (lane & 15);
    int cuA = lane >> 4;
    uint32_t rbA = (uint32_t)rA * 128u;
    int xA = rA & 7;
    int rB = (lane & 7) + ((lane & 16) >> 1);
    int cB = (lane >> 3) & 1;
    uint32_t uB = (uint32_t)rB * 128u;
    int xB = rB & 7;

    for (int s = 0; s < 12; s++) {
        if (s + 1 < 12) {
            PJ_LOAD((s + 1) & 1, (s + 1) * 64);
            CP_WAIT(1);
        } else {
            CP_WAIT(0);
        }
        __syncthreads();
        uint32_t base = sb + (s & 1) * PJ_STG;
#pragma unroll
        for (int kk = 0; kk < 4; kk++) {
            uint32_t Ah[4];
            uint32_t aoff = rbA + (uint32_t)(((kk * 2 + cuA) ^ xA) << 4);
            ldsm4(Ah, base + aoff);
            uint32_t coff = (uint32_t)(((kk * 2 + cB) ^ xB) << 4);
            uint32_t bh[8][4];
#pragma unroll
            for (int p = 0; p < 8; p++) ldsm4(bh[p], base + 16384 + p * 2048 + uB + coff);
#pragma unroll
            for (int p = 0; p < 8; p++) {
                mma_f16(acc[2 * p], Ah, &bh[p][0]);
                mma_f16(acc[2 * p + 1], Ah, &bh[p][2]);
            }
        }
        __syncthreads();
    }

    // epilogue: +bias; q additionally scaled by 0.5 (tanh half-scale folded)
    __half* dst = half ? g_kf : g_qf;
    float scale = half ? 1.0f : 0.5f;
    int r0 = row0 + 16 * w + (lane >> 2);
#pragma unroll
    for (int nb = 0; nb < 16; nb++) {
        int c = nb * 8 + (lane & 3) * 2;
        float b0 = g_bqk[half * 128 + c];
        float b1 = g_bqk[half * 128 + c + 1];
        *(__half2*)(dst + (long)r0 * DD + c) =
            __floats2half2_rn(scale * (acc[nb][0] + b0), scale * (acc[nb][1] + b1));
        *(__half2*)(dst + (long)(r0 + 8) * DD + c) =
            __floats2half2_rn(scale * (acc[nb][2] + b0), scale * (acc[nb][3] + b1));
    }
}

// ---------------- attention: persistent HMMA, 4x2 warp tiling ---------
// (R14 structure verbatim — best measured config.)
#define KBUF   32768
#define SO_US  65536
#define AT_SMEM (SO_US + 1024)

__global__ __launch_bounds__(256, 1) void k_attn(float* __restrict__ out) {
    extern __shared__ char smem[];
    uint32_t sb = smem_u32(smem);
    int tid = threadIdx.x, lane = tid & 31, w = tid >> 5;
    int mw = w & 3;       // m position: rows mw*32 .. mw*32+31
    int nw = w >> 2;      // n position: cols nw*64 .. nw*64+63

    int start = (int)((long)blockIdx.x * NITEMS / gridDim.x);
    int end = (int)((long)(blockIdx.x + 1) * NITEMS / gridDim.x);

    // preload K tile + u for first item into buf 0
    {
        int jt = start & (NJT - 1);
        const __half* sh = g_kf + (long)jt * BN * DD;
#pragma unroll
        for (int t = 0; t < 8; t++) {
            int idx = t * 256 + tid;
            int r = idx >> 4, cu = idx & 15;
            uint32_t off = (uint32_t)r * 256u + (uint32_t)((cu ^ (r & 7)) << 4);
            CP_ASYNC16(sb + off, sh + (long)r * DD + cu * 8);
        }
        if (tid < 32) CP_ASYNC16(sb + SO_US + tid * 16, g_u + jt * BN + tid * 4);
        CP_COMMIT();
    }

    int rB = (lane & 7) + ((lane & 16) >> 1);
    int cB = (lane >> 3) & 1;
    uint32_t uB = (uint32_t)rB * 256u;
    int xB = rB & 7;
    const int cl = (lane & 3) * 2;

    uint32_t Ah[2][8][4];               // 2 m-frags x 8 ksteps
    float o00 = 0.f, o01 = 0.f, o10 = 0.f, o11 = 0.f;
    int it = -1;

    for (int idx = start; idx < end; idx++) {
        int b = (idx - start) & 1;
        __syncthreads();  // all warps done with buf b^1 (prev tile)
        if (idx + 1 < end) {
            int jn = (idx + 1) & (NJT - 1);
            uint32_t kb = sb + (b ^ 1) * KBUF;
            const __half* sh = g_kf + (long)jn * BN * DD;
#pragma unroll
            for (int t = 0; t < 8; t++) {
                int i2 = t * 256 + tid;
                int r = i2 >> 4, cu = i2 & 15;
                uint32_t off = (uint32_t)r * 256u + (uint32_t)((cu ^ (r & 7)) << 4);
                CP_ASYNC16(kb + off, sh + (long)r * DD + cu * 8);
            }
            if (tid < 32) CP_ASYNC16(sb + SO_US + (b ^ 1) * 512 + tid * 16, g_u + jn * BN + tid * 4);
            CP_COMMIT();
            CP_WAIT(1);
        } else {
            CP_WAIT(0);
        }
        __syncthreads();

        if ((idx >> 7) != it) {
            if (it >= 0) {
#pragma unroll
                for (int s = 1; s <= 2; s <<= 1) {
                    o00 += __shfl_xor_sync(0xFFFFFFFFu, o00, s);
                    o01 += __shfl_xor_sync(0xFFFFFFFFu, o01, s);
                    o10 += __shfl_xor_sync(0xFFFFFFFFu, o10, s);
                    o11 += __shfl_xor_sync(0xFFFFFFFFu, o11, s);
                }
                if ((lane & 3) == 0) {
                    int r = it * 128 + mw * 32 + (lane >> 2);
                    atomicAdd(out + r, o00);
                    atomicAdd(out + r + 8, o01);
                    atomicAdd(out + r + 16, o10);
                    atomicAdd(out + r + 24, o11);
                }
            }
            it = idx >> 7;
            o00 = 0.f; o01 = 0.f; o10 = 0.f; o11 = 0.f;
#pragma unroll
            for (int mf = 0; mf < 2; mf++) {
                const __half* qb =
                    g_qf + ((long)it * 128 + mw * 32 + mf * 16 + (lane >> 2)) * DD + cl;
#pragma unroll
                for (int kk = 0; kk < 8; kk++) {
                    Ah[mf][kk][0] = *(const uint32_t*)(qb + kk * 16);
                    Ah[mf][kk][1] = *(const uint32_t*)(qb + 8 * DD + kk * 16);
                    Ah[mf][kk][2] = *(const uint32_t*)(qb + kk * 16 + 8);
                    Ah[mf][kk][3] = *(const uint32_t*)(qb + 8 * DD + kk * 16 + 8);
                }
            }
        }

        uint32_t kb = sb + b * KBUF + nw * 16384;  // this warp's 64-col half
        float acc[2][8][4];
#pragma unroll
        for (int mf = 0; mf < 2; mf++)
#pragma unroll
            for (int nb = 0; nb < 8; nb++) {
                acc[mf][nb][0] = 0.f; acc[mf][nb][1] = 0.f;
                acc[mf][nb][2] = 0.f; acc[mf][nb][3] = 0.f;
            }

#pragma unroll
        for (int kk = 0; kk < 8; kk++) {
            uint32_t coff = (uint32_t)(((kk * 2 + cB) ^ xB) << 4);
            uint32_t bh[4][4];
#pragma unroll
            for (int p = 0; p < 4; p++) ldsm4(bh[p], kb + p * 4096 + uB + coff);
#pragma unroll
            for (int p = 0; p < 4; p++) {
                mma_f16(acc[0][2 * p], Ah[0][kk], &bh[p][0]);
                mma_f16(acc[0][2 * p + 1], Ah[0][kk], &bh[p][2]);
                mma_f16(acc[1][2 * p], Ah[1][kk], &bh[p][0]);
                mma_f16(acc[1][2 * p + 1], Ah[1][kk], &bh[p][2]);
            }
        }

        // sigmoid: sig*u = uh*tanh(0.5 s) + uh  (0.5 folded into q and g_u)
        const float* Us = (const float*)(smem + SO_US + b * 512) + nw * 64;
        float ts = 0.f;
#pragma unroll
        for (int nb = 0; nb < 8; nb++) {
            float2 u2 = *(const float2*)(Us + nb * 8 + cl);
            ts += u2.x + u2.y;
            float t0 = tanh_ap(acc[0][nb][0]);
            float t1 = tanh_ap(acc[0][nb][1]);
            float t2 = tanh_ap(acc[0][nb][2]);
            float t3 = tanh_ap(acc[0][nb][3]);
            o00 = fmaf(t0, u2.x, o00); o00 = fmaf(t1, u2.y, o00);
            o01 = fmaf(t2, u2.x, o01); o01 = fmaf(t3, u2.y, o01);
            t0 = tanh_ap(acc[1][nb][0]);
            t1 = tanh_ap(acc[1][nb][1]);
            t2 = tanh_ap(acc[1][nb][2]);
            t3 = tanh_ap(acc[1][nb][3]);
            o10 = fmaf(t0, u2.x, o10); o10 = fmaf(t1, u2.y, o10);
            o11 = fmaf(t2, u2.x, o11); o11 = fmaf(t3, u2.y, o11);
        }
        o00 += ts; o01 += ts; o10 += ts; o11 += ts;
    }

#pragma unroll
    for (int s = 1; s <= 2; s <<= 1) {
        o00 += __shfl_xor_sync(0xFFFFFFFFu, o00, s);
        o01 += __shfl_xor_sync(0xFFFFFFFFu, o01, s);
        o10 += __shfl_xor_sync(0xFFFFFFFFu, o10, s);
        o11 += __shfl_xor_sync(0xFFFFFFFFu, o11, s);
    }
    if (it >= 0 && (lane & 3) == 0) {
        int r = it * 128 + mw * 32 + (lane >> 2);
        atomicAdd(out + r, o00);
        atomicAdd(out + r + 8, o01);
        atomicAdd(out + r + 16, o10);
        atomicAdd(out + r + 24, o11);
    }
}

// ---------------- launch ----------------------------------------------
extern "C" void kernel_launch(void* const* d_in, const int* in_sizes, int n_in,
                              void* d_out, int out_size) {
    const float* x       = (const float*)d_in[0];
    const float* W_token = (const float*)d_in[2];
    const float* b_token = (const float*)d_in[3];
    const float* W_qkv   = (const float*)d_in[4];
    const float* b_qkv   = (const float*)d_in[5];
    const float* W_fc    = (const float*)d_in[6];
    const float* b_fc    = (const float*)d_in[7];
    float* out = (float*)d_out;

    int nsm = 148;
    cudaDeviceGetAttribute(&nsm, cudaDevAttrMultiProcessorCount, 0);

    cudaFuncSetAttribute(k_attn, cudaFuncAttributeMaxDynamicSharedMemorySize, AT_SMEM);
    cudaFuncSetAttribute(k_projh, cudaFuncAttributeMaxDynamicSharedMemorySize, PJ_SMEM);

    k_pre<<<769, 384>>>(W_token, b_token, W_qkv, b_qkv, W_fc);  // launch 1
    k_xu<<<NROWS / 8, 256>>>(x);                                // launch 2
    k_projh<<<dim3(128, 2), 256, PJ_SMEM>>>(b_fc, out);         // launch 3
    k_attn<<<nsm, 256, AT_SMEM>>>(out);                         // launch 4 (profiled)
}

// round 17
// speedup vs baseline: 1.1127x; 1.0192x over previous
#include <cuda_runtime.h>
#include <cuda_fp16.h>
#include <cstdint>

#define NROWS 16384
#define INDIM 768
#define DD    128
#define NITEMS2 (128 * 256)   // 128 row-tiles x 256 k-chunks (64 cols)

// ---------------- device scratch (no allocs allowed) ----------------
__device__ float g_wu[INDIM];
__device__ float g_bqk[256];
__device__ float g_bu;
__device__ float g_u[NROWS];   // stores 0.5*u (sig*u = uh*tanh(0.5s) + uh)
__device__ __align__(16) __half g_xhi[NROWS * INDIM];
__device__ __align__(16) __half g_wTh[256 * INDIM];
__device__ __align__(16) __half g_qf[NROWS * DD];   // stores 0.5*q
__device__ __align__(16) __half g_kf[NROWS * DD];

// ---------------- PTX helpers (base ISA only) -------------------------
__device__ __forceinline__ uint32_t smem_u32(const void* p) {
    uint32_t a;
    asm("{ .reg .u64 t; cvta.to.shared.u64 t, %1; cvt.u32.u64 %0, t; }" : "=r"(a) : "l"(p));
    return a;
}
#define CP_ASYNC16(dst, src) asm volatile("cp.async.cg.shared.global [%0], [%1], 16;" :: "r"(dst), "l"(src) : "memory")
#define CP_COMMIT()          asm volatile("cp.async.commit_group;" ::: "memory")
#define CP_WAIT(n)           asm volatile("cp.async.wait_group %0;" :: "n"(n) : "memory")

__device__ __forceinline__ void ldsm4(uint32_t* r, uint32_t addr) {
    asm volatile("ldmatrix.sync.aligned.m8n8.x4.shared.b16 {%0,%1,%2,%3}, [%4];"
                 : "=r"(r[0]), "=r"(r[1]), "=r"(r[2]), "=r"(r[3]) : "r"(addr));
}
__device__ __forceinline__ void mma_f16(float* c, const uint32_t* a, const uint32_t* b) {
    asm volatile("mma.sync.aligned.m16n8k16.row.col.f32.f16.f16.f32 "
                 "{%0,%1,%2,%3}, {%4,%5,%6,%7}, {%8,%9}, {%0,%1,%2,%3};"
                 : "+f"(c[0]), "+f"(c[1]), "+f"(c[2]), "+f"(c[3])
                 : "r"(a[0]), "r"(a[1]), "r"(a[2]), "r"(a[3]), "r"(b[0]), "r"(b[1]));
}
__device__ __forceinline__ float tanh_ap(float x) {
    float r;
    asm("tanh.approx.f32 %0, %1;" : "=f"(r) : "f"(x));
    return r;
}

// ---------------- k_pre: all weight precompute in one launch -----------
__global__ __launch_bounds__(384) void k_pre(const float* __restrict__ W_token,
                                             const float* __restrict__ b_token,
                                             const float* __restrict__ W_qkv,
                                             const float* __restrict__ b_qkv,
                                             const float* __restrict__ W_fc) {
    __shared__ float wt[DD];
    __shared__ float vcol[DD];
    int t = blockIdx.x, n = threadIdx.x;
    bool isb = (t == 768);
    if (n < DD) wt[n] = isb ? b_token[n] : W_token[t * DD + n];
    __syncthreads();
    float acc = 0.f;
    for (int d = 0; d < DD; d++) acc += wt[d] * W_qkv[d * 3 * DD + n];
    if (isb) acc += b_qkv[n];
    if (n < 256) {
        if (isb) g_bqk[n] = acc;
        else g_wTh[n * INDIM + t] = __float2half_rn(acc);
    } else {
        vcol[n - 256] = acc;
    }
    __syncthreads();
    if (n < 32) {
        float a = 0.f;
#pragma unroll
        for (int i = 0; i < 4; i++) a += vcol[n + 32 * i] * W_fc[n + 32 * i];
#pragma unroll
        for (int off = 16; off; off >>= 1) a += __shfl_xor_sync(0xFFFFFFFFu, a, off);
        if (n == 0) {
            if (isb) g_bu = a;
            else g_wu[t] = a;
        }
    }
}

// ---------------- x -> fp16 split + u matvec (one warp per row) --------
__global__ __launch_bounds__(256) void k_xu(const float* __restrict__ x) {
    int row = blockIdx.x * 8 + (threadIdx.x >> 5);
    int lane = threadIdx.x & 31;
    const float* xr = x + (long)row * INDIM;
    __half* xh = g_xhi + (long)row * INDIM;
    float acc = 0.f;
#pragma unroll
    for (int i = 0; i < 6; i++) {
        int c = i * 128 + lane * 4;
        float4 v = *(const float4*)(xr + c);
        float4 wv = *(const float4*)(g_wu + c);
        acc += v.x * wv.x + v.y * wv.y + v.z * wv.z + v.w * wv.w;
        *(__half2*)(xh + c) = __floats2half2_rn(v.x, v.y);
        *(__half2*)(xh + c + 2) = __floats2half2_rn(v.z, v.w);
    }
#pragma unroll
    for (int off = 16; off; off >>= 1) acc += __shfl_xor_sync(0xFFFFFFFFu, acc, off);
    if (lane == 0) g_u[row] = 0.5f * (acc + g_bu);
}

// ---------------- projection GEMM (HMMA fp16, 1 pass per half) ---------
#define PJ_STG  32768
#define PJ_SMEM (2 * PJ_STG)
__global__ __launch_bounds__(256, 1) void k_projh(const float* __restrict__ b_fc,
                                                  float* __restrict__ out) {
    extern __shared__ char smem[];
    uint32_t sb = smem_u32(smem);
    int tid = threadIdx.x, lane = tid & 31, w = tid >> 5;
    int row0 = blockIdx.x * 128;
    int half = blockIdx.y;
    const __half* wh = g_wTh + (long)half * 128 * INDIM;

    if (half == 0 && tid < 128) out[row0 + tid] = b_fc[0];

#define PJ_LOAD(buf, kc)                                                          \
    do {                                                                          \
        uint32_t base_ = sb + (buf) * PJ_STG;                                     \
        _Pragma("unroll")                                                         \
        for (int t_ = 0; t_ < 4; t_++) {                                          \
            int idx_ = t_ * 256 + tid;                                            \
            int r_ = idx_ >> 3, cu_ = idx_ & 7;                                   \
            uint32_t off_ = (uint32_t)r_ * 128u + (uint32_t)((cu_ ^ (r_ & 7)) << 4); \
            CP_ASYNC16(base_ + off_,         g_xhi + (long)(row0 + r_) * INDIM + (kc) + cu_ * 8); \
            CP_ASYNC16(base_ + 16384 + off_, wh + (long)r_ * INDIM + (kc) + cu_ * 8); \
        }                                                                         \
        CP_COMMIT();                                                              \
    } while (0)

    PJ_LOAD(0, 0);

    float acc[16][4];
#pragma unroll
    for (int nb = 0; nb < 16; nb++) {
        acc[nb][0] = 0.f; acc[nb][1] = 0.f; acc[nb][2] = 0.f; acc[nb][3] = 0.f;
    }

    int rA = 16 * w + (lane & 15);
    int cuA = lane >> 4;
    uint32_t rbA = (uint32_t)rA * 128u;
    int xA = rA & 7;
    int rB = (lane & 7) + ((lane & 16) >> 1);
    int cB = (lane >> 3) & 1;
    uint32_t uB = (uint32_t)rB * 128u;
    int xB = rB & 7;

    for (int s = 0; s < 12; s++) {
        if (s + 1 < 12) {
            PJ_LOAD((s + 1) & 1, (s + 1) * 64);
            CP_WAIT(1);
        } else {
            CP_WAIT(0);
        }
        __syncthreads();
        uint32_t base = sb + (s & 1) * PJ_STG;
#pragma unroll
        for (int kk = 0; kk < 4; kk++) {
            uint32_t Ah[4];
            uint32_t aoff = rbA + (uint32_t)(((kk * 2 + cuA) ^ xA) << 4);
            ldsm4(Ah, base + aoff);
            uint32_t coff = (uint32_t)(((kk * 2 + cB) ^ xB) << 4);
            uint32_t bh[8][4];
#pragma unroll
            for (int p = 0; p < 8; p++) ldsm4(bh[p], base + 16384 + p * 2048 + uB + coff);
#pragma unroll
            for (int p = 0; p < 8; p++) {
                mma_f16(acc[2 * p], Ah, &bh[p][0]);
                mma_f16(acc[2 * p + 1], Ah, &bh[p][2]);
            }
        }
        __syncthreads();
    }

    __half* dst = half ? g_kf : g_qf;
    float scale = half ? 1.0f : 0.5f;
    int r0 = row0 + 16 * w + (lane >> 2);
#pragma unroll
    for (int nb = 0; nb < 16; nb++) {
        int c = nb * 8 + (lane & 3) * 2;
        float b0 = g_bqk[half * 128 + c];
        float b1 = g_bqk[half * 128 + c + 1];
        *(__half2*)(dst + (long)r0 * DD + c) =
            __floats2half2_rn(scale * (acc[nb][0] + b0), scale * (acc[nb][1] + b1));
        *(__half2*)(dst + (long)(r0 + 8) * DD + c) =
            __floats2half2_rn(scale * (acc[nb][2] + b0), scale * (acc[nb][3] + b1));
    }
}

// ---------------- attention: 2 CTAs/SM, Q in smem, 32x32 warp tiles ----
// Item = 128 q-rows x 64 k-cols. CTA = 8 warps in 4m x 2n grid.
// Q tile (32KB) lives in smem, reloaded on row-tile change (rare).
// K chunks double buffered (2x16KB). Low regs -> 2 CTAs co-resident.
#define SO_Q   0
#define SO_K   32768
#define SO_US  65536
#define AT_SMEM (SO_US + 1024)

__global__ __launch_bounds__(256, 2) void k_attn(float* __restrict__ out) {
    extern __shared__ char smem[];
    uint32_t sb = smem_u32(smem);
    int tid = threadIdx.x, lane = tid & 31, w = tid >> 5;
    int mw = w & 3;       // m: rows mw*32..+31
    int nw = w >> 2;      // n: cols nw*32..+31 of the 64-col chunk

    int start = (int)((long)blockIdx.x * NITEMS2 / gridDim.x);
    int end = (int)((long)(blockIdx.x + 1) * NITEMS2 / gridDim.x);

    int rA = lane & 15, cuA = lane >> 4;
    int xA = rA & 7;
    uint32_t uA0 = (uint32_t)(mw * 32 + rA) * 256u;
    uint32_t uA1 = uA0 + 16 * 256u;
    int rB = (lane & 7) + ((lane & 16) >> 1);
    int cB = (lane >> 3) & 1;
    int xB = rB & 7;
    uint32_t uB0 = (uint32_t)(nw * 32 + rB) * 256u;
    uint32_t uB1 = uB0 + 16 * 256u;
    const int cl = (lane & 3) * 2;

    float o00 = 0.f, o01 = 0.f, o10 = 0.f, o11 = 0.f;
    int it = -1;

#define FLUSH()                                                                 \
    do {                                                                        \
        _Pragma("unroll")                                                       \
        for (int s_ = 1; s_ <= 2; s_ <<= 1) {                                   \
            o00 += __shfl_xor_sync(0xFFFFFFFFu, o00, s_);                       \
            o01 += __shfl_xor_sync(0xFFFFFFFFu, o01, s_);                       \
            o10 += __shfl_xor_sync(0xFFFFFFFFu, o10, s_);                       \
            o11 += __shfl_xor_sync(0xFFFFFFFFu, o11, s_);                       \
        }                                                                       \
        if ((lane & 3) == 0) {                                                  \
            int r_ = it * 128 + mw * 32 + (lane >> 2);                          \
            atomicAdd(out + r_, o00);                                           \
            atomicAdd(out + r_ + 8, o01);                                       \
            atomicAdd(out + r_ + 16, o10);                                      \
            atomicAdd(out + r_ + 24, o11);                                      \
        }                                                                       \
    } while (0)

    // preload K chunk + u for first item into buf 0
    if (start < end) {
        int jc = start & 255;
        const __half* sh = g_kf + (long)jc * 64 * DD;
#pragma unroll
        for (int t = 0; t < 4; t++) {
            int i2 = t * 256 + tid;
            int r = i2 >> 4, cu = i2 & 15;
            uint32_t off = (uint32_t)r * 256u + (uint32_t)((cu ^ (r & 7)) << 4);
            CP_ASYNC16(sb + SO_K + off, sh + (long)r * DD + cu * 8);
        }
        if (tid < 16) CP_ASYNC16(sb + SO_US + tid * 16, g_u + jc * 64 + tid * 4);
        CP_COMMIT();
    }

    for (int idx = start; idx < end; idx++) {
        int b = (idx - start) & 1;
        __syncthreads();   // everyone done reading buf b^1 and Q (prev item)
        bool hn = (idx + 1 < end);
        if (hn) {
            int jn = (idx + 1) & 255;
            uint32_t kb = sb + SO_K + (b ^ 1) * 16384;
            const __half* sh = g_kf + (long)jn * 64 * DD;
#pragma unroll
            for (int t = 0; t < 4; t++) {
                int i2 = t * 256 + tid;
                int r = i2 >> 4, cu = i2 & 15;
                uint32_t off = (uint32_t)r * 256u + (uint32_t)((cu ^ (r & 7)) << 4);
                CP_ASYNC16(kb + off, sh + (long)r * DD + cu * 8);
            }
            if (tid < 16) CP_ASYNC16(sb + SO_US + (b ^ 1) * 512 + tid * 16,
                                     g_u + jn * 64 + tid * 4);
            CP_COMMIT();
        }
        int nit = idx >> 8;
        if (nit != it) {
            // row-tile change: flush output, load Q tile into smem
            if (it >= 0) FLUSH();
            it = nit;
            o00 = 0.f; o01 = 0.f; o10 = 0.f; o11 = 0.f;
            const __half* qs = g_qf + (long)it * 128 * DD;
#pragma unroll
            for (int t = 0; t < 8; t++) {
                int i2 = t * 256 + tid;
                int r = i2 >> 4, cu = i2 & 15;
                uint32_t off = (uint32_t)r * 256u + (uint32_t)((cu ^ (r & 7)) << 4);
                CP_ASYNC16(sb + SO_Q + off, qs + (long)r * DD + cu * 8);
            }
            CP_COMMIT();
            CP_WAIT(0);   // drains Q + current K (+ next-K early; rare, fine)
        } else {
            if (hn) CP_WAIT(1); else CP_WAIT(0);
        }
        __syncthreads();

        uint32_t kb = sb + SO_K + b * 16384;
        float acc[2][4][4];
#pragma unroll
        for (int mf = 0; mf < 2; mf++)
#pragma unroll
            for (int nb = 0; nb < 4; nb++) {
                acc[mf][nb][0] = 0.f; acc[mf][nb][1] = 0.f;
                acc[mf][nb][2] = 0.f; acc[mf][nb][3] = 0.f;
            }

#pragma unroll
        for (int kk = 0; kk < 8; kk++) {
            uint32_t au = (uint32_t)(((kk * 2 + cuA) ^ xA) << 4);
            uint32_t a0[4], a1[4];
            ldsm4(a0, sb + SO_Q + uA0 + au);
            ldsm4(a1, sb + SO_Q + uA1 + au);
            uint32_t bu = (uint32_t)(((kk * 2 + cB) ^ xB) << 4);
            uint32_t b0[4], b1[4];
            ldsm4(b0, kb + uB0 + bu);
            ldsm4(b1, kb + uB1 + bu);
            mma_f16(acc[0][0], a0, &b0[0]); mma_f16(acc[0][1], a0, &b0[2]);
            mma_f16(acc[0][2], a0, &b1[0]); mma_f16(acc[0][3], a0, &b1[2]);
            mma_f16(acc[1][0], a1, &b0[0]); mma_f16(acc[1][1], a1, &b0[2]);
            mma_f16(acc[1][2], a1, &b1[0]); mma_f16(acc[1][3], a1, &b1[2]);
        }

        // sigmoid: sig*u = uh*tanh(0.5 s) + uh  (0.5 folded into q and g_u)
        const float* Us = (const float*)(smem + SO_US + b * 512) + nw * 32;
        float ts = 0.f;
#pragma unroll
        for (int nb = 0; nb < 4; nb++) {
            float2 u2 = *(const float2*)(Us + nb * 8 + cl);
            ts += u2.x + u2.y;
            float t0 = tanh_ap(acc[0][nb][0]);
            float t1 = tanh_ap(acc[0][nb][1]);
            float t2 = tanh_ap(acc[0][nb][2]);
            float t3 = tanh_ap(acc[0][nb][3]);
            o00 = fmaf(t0, u2.x, o00); o00 = fmaf(t1, u2.y, o00);
            o01 = fmaf(t2, u2.x, o01); o01 = fmaf(t3, u2.y, o01);
            t0 = tanh_ap(acc[1][nb][0]);
            t1 = tanh_ap(acc[1][nb][1]);
            t2 = tanh_ap(acc[1][nb][2]);
            t3 = tanh_ap(acc[1][nb][3]);
            o10 = fmaf(t0, u2.x, o10); o10 = fmaf(t1, u2.y, o10);
            o11 = fmaf(t2, u2.x, o11); o11 = fmaf(t3, u2.y, o11);
        }
        o00 += ts; o01 += ts; o10 += ts; o11 += ts;
    }

    if (it >= 0) FLUSH();
}

// ---------------- launch ----------------------------------------------
extern "C" void kernel_launch(void* const* d_in, const int* in_sizes, int n_in,
                              void* d_out, int out_size) {
    const float* x       = (const float*)d_in[0];
    const float* W_token = (const float*)d_in[2];
    const float* b_token = (const float*)d_in[3];
    const float* W_qkv   = (const float*)d_in[4];
    const float* b_qkv   = (const float*)d_in[5];
    const float* W_fc    = (const float*)d_in[6];
    const float* b_fc    = (const float*)d_in[7];
    float* out = (float*)d_out;

    int nsm = 148;
    cudaDeviceGetAttribute(&nsm, cudaDevAttrMultiProcessorCount, 0);

    cudaFuncSetAttribute(k_attn, cudaFuncAttributeMaxDynamicSharedMemorySize, AT_SMEM);
    cudaFuncSetAttribute(k_projh, cudaFuncAttributeMaxDynamicSharedMemorySize, PJ_SMEM);

    k_pre<<<769, 384>>>(W_token, b_token, W_qkv, b_qkv, W_fc);  // launch 1
    k_xu<<<NROWS / 8, 256>>>(x);                                // launch 2
    k_projh<<<dim3(128, 2), 256, PJ_SMEM>>>(b_fc, out);         // launch 3
    k_attn<<<2 * nsm, 256, AT_SMEM>>>(out);                     // launch 4 (profiled)
}